// round 2
// baseline (speedup 1.0000x reference)
#include <cuda_runtime.h>
#include <math.h>

// Problem constants
#define BB   8
#define NL   64
#define NT   512
#define KDIM 256          // 2*C input features
#define NH   256          // concatenated hidden (128 A + 128 B)
#define TM   64           // rows per CTA
#define NBLK ((BB*NL*NT)/TM)   // 4096

// Per-block partial sums [block][4] : vdw, hbond_raw, metal_raw, hphob_raw
__device__ float g_partial[NBLK][4];

// ---- packed f32x2 helpers (sm_103a FFMA2 path; ptxas never auto-fuses) ----
__device__ __forceinline__ unsigned long long pack2(float lo, float hi) {
    unsigned long long r;
    asm("mov.b64 %0, {%1, %2};" : "=l"(r) : "f"(lo), "f"(hi));
    return r;
}
__device__ __forceinline__ void unpack2(unsigned long long v, float& lo, float& hi) {
    asm("mov.b64 {%0, %1}, %2;" : "=f"(lo), "=f"(hi) : "l"(v));
}
__device__ __forceinline__ void ffma2(unsigned long long& d,
                                      unsigned long long a,
                                      unsigned long long b) {
    asm("fma.rn.f32x2 %0, %1, %2, %0;" : "+l"(d) : "l"(a), "l"(b));
}

__global__ __launch_bounds__(256, 2)
void energy_fused_kernel(
    const float* __restrict__ lig_pos,   // [B,NL,3]
    const float* __restrict__ tgt_pos,   // [B,NT,3]
    const float* __restrict__ lig_r,     // [B,NL]
    const float* __restrict__ tgt_r,     // [B,NT]
    const float* __restrict__ lig_nm,    // [B,NL]
    const float* __restrict__ tgt_nm,    // [B,NT]
    const float* __restrict__ inter,     // [B,3,NL,NT]
    const float* __restrict__ h_cat,     // [B*NL*NT, 256]
    const float* __restrict__ WA1,       // [256,128]
    const float* __restrict__ bA1,       // [128]
    const float* __restrict__ WA2,       // [128]
    const float* __restrict__ bA2,       // [1]
    const float* __restrict__ WB1,       // [256,128]
    const float* __restrict__ bB1,       // [128]
    const float* __restrict__ WB2,       // [128]
    const float* __restrict__ bB2)       // [1]
{
    __shared__ float Xs[16][TM];       // [k][row]
    __shared__ float Ws[16][NH];       // [k][j]
    __shared__ float red[TM][33];      // row partial dots (padded)
    __shared__ float blockred[2][4];

    const int tid = threadIdx.x;
    const int ty  = tid >> 5;          // 0..7  (row group)
    const int tx  = tid & 31;          // 0..31 (col group)
    const int j0  = tx * 8;
    const long row0 = (long)blockIdx.x * TM;

    // packed accumulators: acc2[i][jp] holds columns (j0+2*jp, j0+2*jp+1) for row ty*8+i
    unsigned long long acc2[8][4];
    #pragma unroll
    for (int jp = 0; jp < 4; jp++) {
        int j = j0 + 2 * jp;
        float blo = (j     < 128) ? bA1[j]       : bB1[j - 128];
        float bhi = (j + 1 < 128) ? bA1[j + 1]   : bB1[j + 1 - 128];
        unsigned long long bp = pack2(blo, bhi);
        #pragma unroll
        for (int i = 0; i < 8; i++) acc2[i][jp] = bp;
    }

    // ---- main GEMM loop over K in chunks of 16 ----
    for (int k0 = 0; k0 < KDIM; k0 += 16) {
        // load X tile (64 rows x 16 k), transposed into Xs[k][row]
        {
            int r  = tid >> 2;             // 0..63
            int kc = (tid & 3) * 4;        // 0,4,8,12
            float4 v = *(const float4*)(h_cat + (row0 + r) * (long)KDIM + k0 + kc);
            Xs[kc + 0][r] = v.x;
            Xs[kc + 1][r] = v.y;
            Xs[kc + 2][r] = v.z;
            Xs[kc + 3][r] = v.w;
        }
        // load W tile (16 k x 256 j) from WA1 | WB1
        #pragma unroll
        for (int it = 0; it < 4; it++) {
            int idx = tid + it * 256;      // 0..1023
            int c   = idx >> 6;            // 0..15
            int jj  = idx & 63;            // float4 column index
            float4 v;
            if (jj < 32) v = *(const float4*)(WA1 + (long)(k0 + c) * 128 + jj * 4);
            else         v = *(const float4*)(WB1 + (long)(k0 + c) * 128 + (jj - 32) * 4);
            *(float4*)(&Ws[c][jj * 4]) = v;
        }
        __syncthreads();

        #pragma unroll
        for (int k = 0; k < 16; k++) {
            float xr[8];
            *(float4*)(xr)     = *(const float4*)(&Xs[k][ty * 8]);
            *(float4*)(xr + 4) = *(const float4*)(&Xs[k][ty * 8 + 4]);
            // w pairs: 8 consecutive floats = 4 x b64, already adjacent in smem
            unsigned long long wp[4];
            {
                // 32-byte aligned (j0 multiple of 8 floats)
                const unsigned long long* wq = (const unsigned long long*)(&Ws[k][j0]);
                ulonglong2 wA = *(const ulonglong2*)(wq);
                ulonglong2 wB = *(const ulonglong2*)(wq + 2);
                wp[0] = wA.x; wp[1] = wA.y; wp[2] = wB.x; wp[3] = wB.y;
            }
            #pragma unroll
            for (int i = 0; i < 8; i++) {
                unsigned long long xi = pack2(xr[i], xr[i]);
                #pragma unroll
                for (int jp = 0; jp < 4; jp++)
                    ffma2(acc2[i][jp], xi, wp[jp]);
            }
        }
        __syncthreads();
    }

    // ---- layer 2: relu + dot with W2, partials per row ----
    {
        float p[8];
        #pragma unroll
        for (int i = 0; i < 8; i++) p[i] = 0.0f;
        #pragma unroll
        for (int jp = 0; jp < 4; jp++) {
            int j = j0 + 2 * jp;
            float w2lo = (j     < 128) ? WA2[j]         : WB2[j - 128];
            float w2hi = (j + 1 < 128) ? WA2[j + 1]     : WB2[j + 1 - 128];
            #pragma unroll
            for (int i = 0; i < 8; i++) {
                float alo, ahi;
                unpack2(acc2[i][jp], alo, ahi);
                p[i] = fmaf(fmaxf(alo, 0.0f), w2lo, p[i]);
                p[i] = fmaf(fmaxf(ahi, 0.0f), w2hi, p[i]);
            }
        }
        #pragma unroll
        for (int i = 0; i < 8; i++)
            red[ty * 8 + i][tx] = p[i];
    }
    __syncthreads();

    // ---- per-pair physics epilogue (threads 0..63, one per row) ----
    if (tid < TM) {
        float v_vdw, v_hb, v_mt, v_hp;
        int r = tid;
        float sA = 0.f, sB = 0.f;
        #pragma unroll
        for (int x = 0; x < 16; x++) { sA += red[r][x]; sB += red[r][x + 16]; }
        float mlpA = sA + bA2[0];
        float mlpB = sB + bB2[0];

        long grow = row0 + r;
        int b   = (int)(grow >> 15);       // / (NL*NT)
        int rem = (int)(grow & 32767);
        int l   = rem >> 9;                // / NT
        int t   = rem & 511;

        const float* lp = lig_pos + ((long)b * NL + l) * 3;
        const float* tp = tgt_pos + ((long)b * NT + t) * 3;
        float dx = lp[0] - tp[0];
        float dy = lp[1] - tp[1];
        float dz = lp[2] - tp[2];
        float dm = sqrtf(dx*dx + dy*dy + dz*dz + 1e-10f);
        if (dm < 0.5f) dm = 1e10f;

        float Bp  = tanhf(mlpB) * 0.2f;
        float dm0 = lig_r[b * NL + l] + tgt_r[b * NT + t] + Bp;
        float dm0c = (dm0 < 1e-4f) ? 1.0f : dm0;
        float ratio = dm0c / dm;
        float r2 = ratio * ratio;
        float r6 = r2 * r2 * r2;
        float vdwe = fminf(fmaf(r6, r6, -2.0f * r6), 100.0f);
        vdwe *= lig_nm[b * NL + l] * tgt_nm[b * NT + t];

        float Av   = 1.0f / (1.0f + expf(-mlpA));
        float Avdw = Av * (0.0356f - 0.0178f) + 0.0178f;
        v_vdw = Avdw * vdwe;

        float d = dm - dm0;
        const float* ib = inter + (long)b * 3 * NL * NT + (long)l * NT + t;
        float I0 = ib[0];
        float I1 = ib[NL * NT];
        float I2 = ib[2 * NL * NT];
        v_hb = fminf(fmaxf(d * I0 * (-1.0f / 0.7f), 0.0f), 1.0f);
        v_mt = fminf(fmaxf(d * I1 * (-1.0f / 0.7f), 0.0f), 1.0f);
        v_hp = fminf(fmaxf((1.5f - d) * I2, 0.0f), 1.0f);

        // warp-level reduction (warps 0 and 1 fully active here)
        #pragma unroll
        for (int off = 16; off > 0; off >>= 1) {
            v_vdw += __shfl_down_sync(0xffffffffu, v_vdw, off);
            v_hb  += __shfl_down_sync(0xffffffffu, v_hb,  off);
            v_mt  += __shfl_down_sync(0xffffffffu, v_mt,  off);
            v_hp  += __shfl_down_sync(0xffffffffu, v_hp,  off);
        }
        if ((tid & 31) == 0) {
            int w = tid >> 5;
            blockred[w][0] = v_vdw;
            blockred[w][1] = v_hb;
            blockred[w][2] = v_mt;
            blockred[w][3] = v_hp;
        }
    }
    __syncthreads();
    if (tid < 4)
        g_partial[blockIdx.x][tid] = blockred[0][tid] + blockred[1][tid];
}

__global__ void energy_reduce_kernel(
    const float* __restrict__ rotor,     // [B]
    const float* __restrict__ hb_c,      // [1]
    const float* __restrict__ hp_c,      // [1]
    const float* __restrict__ rot_c,     // [1]
    float* __restrict__ out)             // [B,4]
{
    // 256 threads: b = tid/32, k = (tid/8)%4, s = tid%8
    int tid = threadIdx.x;
    int b = tid >> 5;
    int k = (tid >> 3) & 3;
    int s = tid & 7;
    const int BLK_PER_B = NBLK / BB;     // 512
    float sum = 0.f;
    for (int i = s; i < BLK_PER_B; i += 8)
        sum += g_partial[b * BLK_PER_B + i][k];
    sum += __shfl_down_sync(0xffffffffu, sum, 4);
    sum += __shfl_down_sync(0xffffffffu, sum, 2);
    sum += __shfl_down_sync(0xffffffffu, sum, 1);
    if (s == 0) {
        float v = sum;
        float hb2 = hb_c[0] * hb_c[0];
        float hp2 = hp_c[0] * hp_c[0];
        if (k == 1 || k == 2) v *= -hb2;
        if (k == 3)           v *= -hp2;
        v /= (1.0f + rot_c[0] * rot_c[0] * rotor[b]);
        out[b * 4 + k] = v;
    }
}

extern "C" void kernel_launch(void* const* d_in, const int* in_sizes, int n_in,
                              void* d_out, int out_size)
{
    const float* lig_pos = (const float*)d_in[0];
    const float* tgt_pos = (const float*)d_in[1];
    const float* lig_r   = (const float*)d_in[2];
    const float* tgt_r   = (const float*)d_in[3];
    const float* lig_nm  = (const float*)d_in[4];
    const float* tgt_nm  = (const float*)d_in[5];
    const float* inter   = (const float*)d_in[6];
    const float* rotor   = (const float*)d_in[7];
    const float* h_cat   = (const float*)d_in[8];
    const float* WA1     = (const float*)d_in[9];
    const float* bA1     = (const float*)d_in[10];
    const float* WA2     = (const float*)d_in[11];
    const float* bA2     = (const float*)d_in[12];
    const float* WB1     = (const float*)d_in[13];
    const float* bB1     = (const float*)d_in[14];
    const float* WB2     = (const float*)d_in[15];
    const float* bB2     = (const float*)d_in[16];
    const float* hb_c    = (const float*)d_in[17];
    const float* hp_c    = (const float*)d_in[18];
    const float* rot_c   = (const float*)d_in[19];
    float* out = (float*)d_out;

    energy_fused_kernel<<<NBLK, 256>>>(
        lig_pos, tgt_pos, lig_r, tgt_r, lig_nm, tgt_nm, inter, h_cat,
        WA1, bA1, WA2, bA2, WB1, bB1, WB2, bB2);
    energy_reduce_kernel<<<1, 256>>>(rotor, hb_c, hp_c, rot_c, out);
}

// round 4
// speedup vs baseline: 4.6168x; 4.6168x over previous
#include <cuda_runtime.h>
#include <math.h>
#include <stdint.h>

// Problem constants
#define BB   8
#define NL   64
#define NT   512
#define KDIM 256
#define MTOT (BB*NL*NT)        // 262144
#define MT   128               // rows per CTA
#define NBLK (MTOT/MT)         // 2048
#define KC   64                // k chunk
#define AST  68                // A smem row stride (floats)
#define BST  68                // B smem row stride (floats)

__device__ float g_partial[NBLK][4];
__device__ float g_Wt[256 * 256];   // [n][k], tf32-rounded bits

__device__ __forceinline__ uint32_t smem_u32(const void* p) {
    uint32_t a;
    asm("{ .reg .u64 t; cvta.to.shared.u64 t, %1; cvt.u32.u64 %0, t; }" : "=r"(a) : "l"(p));
    return a;
}
__device__ __forceinline__ uint32_t f2tf32(float f) {
    uint32_t u;
    asm("cvt.rna.tf32.f32 %0, %1;" : "=r"(u) : "f"(f));
    return u;
}
__device__ __forceinline__ void cp_async16(uint32_t dst, const void* src) {
    asm volatile("cp.async.ca.shared.global [%0], [%1], 16;" :: "r"(dst), "l"(src) : "memory");
}
__device__ __forceinline__ void cp_commit() {
    asm volatile("cp.async.commit_group;" ::: "memory");
}
__device__ __forceinline__ void cp_wait0() {
    asm volatile("cp.async.wait_group 0;" ::: "memory");
}
__device__ __forceinline__ void mma_tf32(float* d, const uint32_t* a, const uint32_t* b) {
    asm volatile(
        "mma.sync.aligned.m16n8k8.row.col.f32.tf32.tf32.f32 "
        "{%0,%1,%2,%3}, {%4,%5,%6,%7}, {%8,%9}, {%0,%1,%2,%3};"
        : "+f"(d[0]), "+f"(d[1]), "+f"(d[2]), "+f"(d[3])
        : "r"(a[0]), "r"(a[1]), "r"(a[2]), "r"(a[3]), "r"(b[0]), "r"(b[1]));
}

// smem layout (bytes):
//  s_bias @0 (1024), s_w2 @1024 (1024), s_red @2048 (2048), s_bred @4096 (128)
//  sA[2] @4224 (+34816 each), sB[2] @4224+69632 (+69632 each)
#define OFF_BIAS 0
#define OFF_W2   1024
#define OFF_RED  2048
#define OFF_BRED 4096
#define OFF_A    4224
#define A_BYTES  (MT*AST*4)        // 34816
#define OFF_B    (OFF_A + 2*A_BYTES)
#define B_BYTES  (256*BST*4)       // 69632
#define SMEM_BYTES (OFF_B + 2*B_BYTES)  // 213120

// ---------------- kernel 0: transpose + tf32-round W ----------------
__global__ void wt_transpose_kernel(const float* __restrict__ WA1,
                                    const float* __restrict__ WB1) {
    int n = blockIdx.x;     // 0..255
    int k = threadIdx.x;    // 0..255
    float v = (n < 128) ? WA1[k * 128 + n] : WB1[k * 128 + (n - 128)];
    ((uint32_t*)g_Wt)[n * 256 + k] = f2tf32(v);
}

// ---------------- main fused kernel ----------------
__global__ __launch_bounds__(512, 1)
void energy_mma_kernel(
    const float* __restrict__ lig_pos, const float* __restrict__ tgt_pos,
    const float* __restrict__ lig_r,   const float* __restrict__ tgt_r,
    const float* __restrict__ lig_nm,  const float* __restrict__ tgt_nm,
    const float* __restrict__ inter,   const float* __restrict__ h_cat,
    const float* __restrict__ bA1, const float* __restrict__ WA2,
    const float* __restrict__ bA2, const float* __restrict__ bB1,
    const float* __restrict__ WB2, const float* __restrict__ bB2)
{
    extern __shared__ char smem[];
    const uint32_t sb = smem_u32(smem);
    const int tid  = threadIdx.x;
    const int wid  = tid >> 5;
    const int lane = tid & 31;
    const int wm   = wid >> 2;     // 0..3 (M)
    const int wn   = wid & 3;      // 0..3 (N)

    float* s_bias = (float*)(smem + OFF_BIAS);
    float* s_w2   = (float*)(smem + OFF_W2);
    float* s_red  = (float*)(smem + OFF_RED);
    float* s_bred = (float*)(smem + OFF_BRED);
    const long row0 = (long)blockIdx.x * MT;

    if (tid < 256) {
        s_bias[tid] = (tid < 128) ? bA1[tid] : bB1[tid - 128];
        s_w2[tid]   = (tid < 128) ? WA2[tid] : WB2[tid - 128];
    }

    // staging for A (LDG -> regs -> cvt -> STS)
    float4 aReg[4];
    const int a_r  = tid >> 2;           // 0..127 (row), 4 float4 per row handled below
    // For A: idx = tid + i*512 -> r = idx>>4, kq = idx&15
    // loadA(c): fill aReg
    // B cp.async: idx = tid + i*512 -> n = idx>>4, kq = idx&15

    auto loadA = [&](int c) {
        #pragma unroll
        for (int i = 0; i < 4; i++) {
            int idx = tid + i * 512;
            int r = idx >> 4, kq = idx & 15;
            aReg[i] = *(const float4*)(h_cat + (row0 + r) * (long)KDIM + c * KC + kq * 4);
        }
    };
    auto stsA = [&](int buf) {
        #pragma unroll
        for (int i = 0; i < 4; i++) {
            int idx = tid + i * 512;
            int r = idx >> 4, kq = idx & 15;
            uint4 u;
            u.x = f2tf32(aReg[i].x); u.y = f2tf32(aReg[i].y);
            u.z = f2tf32(aReg[i].z); u.w = f2tf32(aReg[i].w);
            *(uint4*)(smem + OFF_A + buf * A_BYTES + (r * AST + kq * 4) * 4) = u;
        }
    };
    auto cpB = [&](int c, int buf) {
        uint32_t dstb = sb + OFF_B + buf * B_BYTES;
        #pragma unroll
        for (int i = 0; i < 8; i++) {
            int idx = tid + i * 512;
            int n = idx >> 4, kq = idx & 15;
            cp_async16(dstb + (n * BST + kq * 4) * 4,
                       (const char*)g_Wt + (n * 256 + c * KC + kq * 4) * 4);
        }
        cp_commit();
    };

    // prologue: chunk 0
    loadA(0);
    cpB(0, 0);
    stsA(0);
    cp_wait0();
    __syncthreads();

    float acc[2][8][4];
    #pragma unroll
    for (int mt = 0; mt < 2; mt++)
        #pragma unroll
        for (int nt = 0; nt < 8; nt++)
            #pragma unroll
            for (int e = 0; e < 4; e++) acc[mt][nt][e] = 0.0f;

    const int ar0 = wm * 32 + (lane >> 2);
    const int ak  = lane & 3;
    const int bn0 = wn * 64 + (lane >> 2);

    #pragma unroll 1
    for (int c = 0; c < 4; c++) {
        int buf = c & 1, nbuf = buf ^ 1;
        if (c < 3) { loadA(c + 1); cpB(c + 1, nbuf); }

        const uint32_t* Ab = (const uint32_t*)(smem + OFF_A + buf * A_BYTES);
        const uint32_t* Bb = (const uint32_t*)(smem + OFF_B + buf * B_BYTES);

        #pragma unroll
        for (int ks = 0; ks < 8; ks++) {
            int k0 = ks * 8 + ak;
            uint32_t afr[2][4];
            #pragma unroll
            for (int mt = 0; mt < 2; mt++) {
                int rr = ar0 + mt * 16;
                afr[mt][0] = Ab[rr * AST + k0];
                afr[mt][1] = Ab[(rr + 8) * AST + k0];
                afr[mt][2] = Ab[rr * AST + k0 + 4];
                afr[mt][3] = Ab[(rr + 8) * AST + k0 + 4];
            }
            uint32_t bfr[8][2];
            #pragma unroll
            for (int nt = 0; nt < 8; nt++) {
                int nn = bn0 + nt * 8;
                bfr[nt][0] = Bb[nn * BST + k0];
                bfr[nt][1] = Bb[nn * BST + k0 + 4];
            }
            #pragma unroll
            for (int mt = 0; mt < 2; mt++)
                #pragma unroll
                for (int nt = 0; nt < 8; nt++)
                    mma_tf32(acc[mt][nt], afr[mt], bfr[nt]);
        }

        if (c < 3) { stsA(nbuf); cp_wait0(); }
        __syncthreads();
    }

    // ---- epilogue: relu(acc+bias) . w2, per-row sums ----
    {
        #pragma unroll
        for (int mt = 0; mt < 2; mt++) {
            float p_lo = 0.f, p_hi = 0.f;
            #pragma unroll
            for (int nt = 0; nt < 8; nt++) {
                int cb = wn * 64 + nt * 8 + 2 * (lane & 3);
                float b0 = s_bias[cb],     w0 = s_w2[cb];
                float b1 = s_bias[cb + 1], w1 = s_w2[cb + 1];
                p_lo = fmaf(fmaxf(acc[mt][nt][0] + b0, 0.f), w0, p_lo);
                p_lo = fmaf(fmaxf(acc[mt][nt][1] + b1, 0.f), w1, p_lo);
                p_hi = fmaf(fmaxf(acc[mt][nt][2] + b0, 0.f), w0, p_hi);
                p_hi = fmaf(fmaxf(acc[mt][nt][3] + b1, 0.f), w1, p_hi);
            }
            // reduce over the quad (lanes sharing lane>>2)
            p_lo += __shfl_xor_sync(0xffffffffu, p_lo, 1);
            p_lo += __shfl_xor_sync(0xffffffffu, p_lo, 2);
            p_hi += __shfl_xor_sync(0xffffffffu, p_hi, 1);
            p_hi += __shfl_xor_sync(0xffffffffu, p_hi, 2);
            if ((lane & 3) == 0) {
                int r = wm * 32 + mt * 16 + (lane >> 2);
                s_red[r * 4 + wn]       = p_lo;
                s_red[(r + 8) * 4 + wn] = p_hi;
            }
        }
    }
    __syncthreads();

    // ---- physics epilogue: threads 0..127, one per row ----
    if (tid < MT) {
        int r = tid;
        float sA = s_red[r * 4 + 0] + s_red[r * 4 + 1];
        float sB = s_red[r * 4 + 2] + s_red[r * 4 + 3];
        float mlpA = sA + bA2[0];
        float mlpB = sB + bB2[0];

        long grow = row0 + r;
        int b   = (int)(grow >> 15);
        int rem = (int)(grow & 32767);
        int l   = rem >> 9;
        int t   = rem & 511;

        const float* lp = lig_pos + ((long)b * NL + l) * 3;
        const float* tp = tgt_pos + ((long)b * NT + t) * 3;
        float dx = lp[0] - tp[0];
        float dy = lp[1] - tp[1];
        float dz = lp[2] - tp[2];
        float dm = sqrtf(dx*dx + dy*dy + dz*dz + 1e-10f);
        if (dm < 0.5f) dm = 1e10f;

        float Bp  = tanhf(mlpB) * 0.2f;
        float dm0 = lig_r[b * NL + l] + tgt_r[b * NT + t] + Bp;
        float dm0c = (dm0 < 1e-4f) ? 1.0f : dm0;
        float ratio = dm0c / dm;
        float r2 = ratio * ratio;
        float r6 = r2 * r2 * r2;
        float vdwe = fminf(fmaf(r6, r6, -2.0f * r6), 100.0f);
        vdwe *= lig_nm[b * NL + l] * tgt_nm[b * NT + t];

        float Av   = 1.0f / (1.0f + expf(-mlpA));
        float Avdw = Av * (0.0356f - 0.0178f) + 0.0178f;
        float v_vdw = Avdw * vdwe;

        float d = dm - dm0;
        const float* ib = inter + (long)b * 3 * NL * NT + (long)l * NT + t;
        float I0 = ib[0];
        float I1 = ib[NL * NT];
        float I2 = ib[2 * NL * NT];
        float v_hb = fminf(fmaxf(d * I0 * (-1.0f / 0.7f), 0.0f), 1.0f);
        float v_mt = fminf(fmaxf(d * I1 * (-1.0f / 0.7f), 0.0f), 1.0f);
        float v_hp = fminf(fmaxf((1.5f - d) * I2, 0.0f), 1.0f);

        #pragma unroll
        for (int off = 16; off > 0; off >>= 1) {
            v_vdw += __shfl_down_sync(0xffffffffu, v_vdw, off);
            v_hb  += __shfl_down_sync(0xffffffffu, v_hb,  off);
            v_mt  += __shfl_down_sync(0xffffffffu, v_mt,  off);
            v_hp  += __shfl_down_sync(0xffffffffu, v_hp,  off);
        }
        if (lane == 0) {
            s_bred[wid * 4 + 0] = v_vdw;
            s_bred[wid * 4 + 1] = v_hb;
            s_bred[wid * 4 + 2] = v_mt;
            s_bred[wid * 4 + 3] = v_hp;
        }
    }
    __syncthreads();
    if (tid < 4) {
        float s = 0.f;
        #pragma unroll
        for (int w = 0; w < 4; w++) s += s_bred[w * 4 + tid];
        g_partial[blockIdx.x][tid] = s;
    }
}

// ---------------- final reduce ----------------
__global__ void energy_reduce_kernel(
    const float* __restrict__ rotor, const float* __restrict__ hb_c,
    const float* __restrict__ hp_c,  const float* __restrict__ rot_c,
    float* __restrict__ out)
{
    int tid = threadIdx.x;
    int b = tid >> 5;
    int k = (tid >> 3) & 3;
    int s = tid & 7;
    const int BLK_PER_B = NBLK / BB;    // 256
    float sum = 0.f;
    for (int i = s; i < BLK_PER_B; i += 8)
        sum += g_partial[b * BLK_PER_B + i][k];
    sum += __shfl_down_sync(0xffffffffu, sum, 4);
    sum += __shfl_down_sync(0xffffffffu, sum, 2);
    sum += __shfl_down_sync(0xffffffffu, sum, 1);
    if (s == 0) {
        float v = sum;
        float hb2 = hb_c[0] * hb_c[0];
        float hp2 = hp_c[0] * hp_c[0];
        if (k == 1 || k == 2) v *= -hb2;
        if (k == 3)           v *= -hp2;
        v /= (1.0f + rot_c[0] * rot_c[0] * rotor[b]);
        out[b * 4 + k] = v;
    }
}

extern "C" void kernel_launch(void* const* d_in, const int* in_sizes, int n_in,
                              void* d_out, int out_size)
{
    const float* lig_pos = (const float*)d_in[0];
    const float* tgt_pos = (const float*)d_in[1];
    const float* lig_r   = (const float*)d_in[2];
    const float* tgt_r   = (const float*)d_in[3];
    const float* lig_nm  = (const float*)d_in[4];
    const float* tgt_nm  = (const float*)d_in[5];
    const float* inter   = (const float*)d_in[6];
    const float* rotor   = (const float*)d_in[7];
    const float* h_cat   = (const float*)d_in[8];
    const float* WA1     = (const float*)d_in[9];
    const float* bA1     = (const float*)d_in[10];
    const float* WA2     = (const float*)d_in[11];
    const float* bA2     = (const float*)d_in[12];
    const float* WB1     = (const float*)d_in[13];
    const float* bB1     = (const float*)d_in[14];
    const float* WB2     = (const float*)d_in[15];
    const float* bB2     = (const float*)d_in[16];
    const float* hb_c    = (const float*)d_in[17];
    const float* hp_c    = (const float*)d_in[18];
    const float* rot_c   = (const float*)d_in[19];
    float* out = (float*)d_out;

    cudaFuncSetAttribute(energy_mma_kernel,
                         cudaFuncAttributeMaxDynamicSharedMemorySize, SMEM_BYTES);

    wt_transpose_kernel<<<256, 256>>>(WA1, WB1);
    energy_mma_kernel<<<NBLK, 512, SMEM_BYTES>>>(
        lig_pos, tgt_pos, lig_r, tgt_r, lig_nm, tgt_nm, inter, h_cat,
        bA1, WA2, bA2, bB1, WB2, bB2);
    energy_reduce_kernel<<<1, 256>>>(rotor, hb_c, hp_c, rot_c, out);
}

// round 6
// speedup vs baseline: 7.6711x; 1.6615x over previous
#include <cuda_runtime.h>
#include <cuda_fp16.h>
#include <math.h>
#include <stdint.h>

// Problem constants
#define BB   8
#define NL   64
#define NT   512
#define KDIM 256
#define MTOT (BB*NL*NT)        // 262144
#define MT   128               // rows per CTA
#define NBLK (MTOT/MT)         // 2048
#define KC   64                // k per chunk
#define WST  36                // smem row stride in 32-bit words (32 data + 4 pad)

__device__ float g_partial[NBLK][4];
__device__ __half g_Wt[256 * 256];   // [n][k] fp16

__device__ __forceinline__ uint32_t smem_u32(const void* p) {
    uint32_t a;
    asm("{ .reg .u64 t; cvta.to.shared.u64 t, %1; cvt.u32.u64 %0, t; }" : "=r"(a) : "l"(p));
    return a;
}
__device__ __forceinline__ void cp_async16(uint32_t dst, const void* src) {
    asm volatile("cp.async.ca.shared.global [%0], [%1], 16;" :: "r"(dst), "l"(src) : "memory");
}
__device__ __forceinline__ void cp_commit() {
    asm volatile("cp.async.commit_group;" ::: "memory");
}
__device__ __forceinline__ void cp_wait0() {
    asm volatile("cp.async.wait_group 0;" ::: "memory");
}
__device__ __forceinline__ void mma_f16(float* d, const uint32_t* a, const uint32_t* b) {
    asm volatile(
        "mma.sync.aligned.m16n8k16.row.col.f32.f16.f16.f32 "
        "{%0,%1,%2,%3}, {%4,%5,%6,%7}, {%8,%9}, {%0,%1,%2,%3};"
        : "+f"(d[0]), "+f"(d[1]), "+f"(d[2]), "+f"(d[3])
        : "r"(a[0]), "r"(a[1]), "r"(a[2]), "r"(a[3]), "r"(b[0]), "r"(b[1]));
}

// smem layout (bytes):
#define OFF_BIAS 0
#define OFF_W2   1024
#define OFF_RED  2048
#define OFF_BRED 4096
#define OFF_A    4224
#define A_BYTES  (MT*WST*4)          // 18432 (128 rows x 36 words)
#define OFF_B    (OFF_A + 2*A_BYTES) // 41088
#define B_BYTES  (256*WST*4)         // 36864
#define SMEM_BYTES (OFF_B + 2*B_BYTES)  // 114816

// ---------------- kernel 0: transpose + fp16-round W ----------------
__global__ void wt_transpose_kernel(const float* __restrict__ WA1,
                                    const float* __restrict__ WB1) {
    int n = blockIdx.x;     // 0..255
    int k = threadIdx.x;    // 0..255
    float v = (n < 128) ? WA1[k * 128 + n] : WB1[k * 128 + (n - 128)];
    g_Wt[n * 256 + k] = __float2half_rn(v);
}

// ---------------- main fused kernel ----------------
__global__ __launch_bounds__(512, 1)
void energy_mma_kernel(
    const float* __restrict__ lig_pos, const float* __restrict__ tgt_pos,
    const float* __restrict__ lig_r,   const float* __restrict__ tgt_r,
    const float* __restrict__ lig_nm,  const float* __restrict__ tgt_nm,
    const float* __restrict__ inter,   const float* __restrict__ h_cat,
    const float* __restrict__ bA1, const float* __restrict__ WA2,
    const float* __restrict__ bA2, const float* __restrict__ bB1,
    const float* __restrict__ WB2, const float* __restrict__ bB2)
{
    extern __shared__ char smem[];
    const uint32_t sb = smem_u32(smem);
    const int tid  = threadIdx.x;
    const int wid  = tid >> 5;
    const int lane = tid & 31;
    const int wm   = wid >> 2;     // 0..3 (M)
    const int wn   = wid & 3;      // 0..3 (N)

    float* s_bias = (float*)(smem + OFF_BIAS);
    float* s_w2   = (float*)(smem + OFF_W2);
    float* s_red  = (float*)(smem + OFF_RED);
    float* s_bred = (float*)(smem + OFF_BRED);
    const long row0 = (long)blockIdx.x * MT;

    if (tid < 256) {
        s_bias[tid] = (tid < 128) ? bA1[tid] : bB1[tid - 128];
        s_w2[tid]   = (tid < 128) ? WA2[tid] : WB2[tid - 128];
    }

    // A staging (LDG fp32 -> regs -> cvt fp16 -> STS)
    float4 aReg[4];

    auto loadA = [&](int c) {
        #pragma unroll
        for (int i = 0; i < 4; i++) {
            int idx = tid + i * 512;
            int r = idx >> 4, kq = idx & 15;   // kq: float4 index within 64 k
            aReg[i] = *(const float4*)(h_cat + (row0 + r) * (long)KDIM + c * KC + kq * 4);
        }
    };
    auto stsA = [&](int buf) {
        uint32_t* Aw = (uint32_t*)(smem + OFF_A + buf * A_BYTES);
        #pragma unroll
        for (int i = 0; i < 4; i++) {
            int idx = tid + i * 512;
            int r = idx >> 4, kq = idx & 15;
            __half2 h01 = __floats2half2_rn(aReg[i].x, aReg[i].y);
            __half2 h23 = __floats2half2_rn(aReg[i].z, aReg[i].w);
            uint2 u;
            u.x = *(uint32_t*)&h01;
            u.y = *(uint32_t*)&h23;
            *(uint2*)(Aw + r * WST + kq * 2) = u;
        }
    };
    // B: 256 rows x 64 halves = 128B/row = 8 x 16B chunks -> 2048 transfers
    auto cpB = [&](int c, int buf) {
        uint32_t dstb = sb + OFF_B + buf * B_BYTES;
        #pragma unroll
        for (int i = 0; i < 4; i++) {
            int idx = tid + i * 512;       // 0..2047
            int n = idx >> 3, kq = idx & 7;
            cp_async16(dstb + (n * WST + kq * 4) * 4,
                       (const char*)(g_Wt + n * 256 + c * KC + kq * 8));
        }
        cp_commit();
    };

    // prologue: chunk 0
    loadA(0);
    cpB(0, 0);
    stsA(0);
    cp_wait0();
    __syncthreads();

    float acc[2][8][4];
    #pragma unroll
    for (int mt = 0; mt < 2; mt++)
        #pragma unroll
        for (int nt = 0; nt < 8; nt++)
            #pragma unroll
            for (int e = 0; e < 4; e++) acc[mt][nt][e] = 0.0f;

    const int ar0 = wm * 32 + (lane >> 2);
    const int ak  = lane & 3;
    const int bn0 = wn * 64 + (lane >> 2);

    #pragma unroll 1
    for (int c = 0; c < 4; c++) {
        int buf = c & 1, nbuf = buf ^ 1;
        if (c < 3) { loadA(c + 1); cpB(c + 1, nbuf); }

        const uint32_t* Ab = (const uint32_t*)(smem + OFF_A + buf * A_BYTES);
        const uint32_t* Bb = (const uint32_t*)(smem + OFF_B + buf * B_BYTES);

        #pragma unroll
        for (int ks = 0; ks < 4; ks++) {       // 4 x k16 = 64
            int kw = ks * 8 + ak;              // word column (2 halves)
            uint32_t afr[2][4];
            #pragma unroll
            for (int mt = 0; mt < 2; mt++) {
                int rr = ar0 + mt * 16;
                afr[mt][0] = Ab[rr * WST + kw];
                afr[mt][1] = Ab[(rr + 8) * WST + kw];
                afr[mt][2] = Ab[rr * WST + kw + 4];
                afr[mt][3] = Ab[(rr + 8) * WST + kw + 4];
            }
            uint32_t bfr[8][2];
            #pragma unroll
            for (int nt = 0; nt < 8; nt++) {
                int nn = bn0 + nt * 8;
                bfr[nt][0] = Bb[nn * WST + kw];
                bfr[nt][1] = Bb[nn * WST + kw + 4];
            }
            #pragma unroll
            for (int mt = 0; mt < 2; mt++)
                #pragma unroll
                for (int nt = 0; nt < 8; nt++)
                    mma_f16(acc[mt][nt], afr[mt], bfr[nt]);
        }

        if (c < 3) { stsA(nbuf); cp_wait0(); }
        __syncthreads();
    }

    // ---- epilogue: relu(acc+bias) . w2, per-row sums ----
    {
        #pragma unroll
        for (int mt = 0; mt < 2; mt++) {
            float p_lo = 0.f, p_hi = 0.f;
            #pragma unroll
            for (int nt = 0; nt < 8; nt++) {
                int cb = wn * 64 + nt * 8 + 2 * (lane & 3);
                float b0 = s_bias[cb],     w0 = s_w2[cb];
                float b1 = s_bias[cb + 1], w1 = s_w2[cb + 1];
                p_lo = fmaf(fmaxf(acc[mt][nt][0] + b0, 0.f), w0, p_lo);
                p_lo = fmaf(fmaxf(acc[mt][nt][1] + b1, 0.f), w1, p_lo);
                p_hi = fmaf(fmaxf(acc[mt][nt][2] + b0, 0.f), w0, p_hi);
                p_hi = fmaf(fmaxf(acc[mt][nt][3] + b1, 0.f), w1, p_hi);
            }
            p_lo += __shfl_xor_sync(0xffffffffu, p_lo, 1);
            p_lo += __shfl_xor_sync(0xffffffffu, p_lo, 2);
            p_hi += __shfl_xor_sync(0xffffffffu, p_hi, 1);
            p_hi += __shfl_xor_sync(0xffffffffu, p_hi, 2);
            if ((lane & 3) == 0) {
                int r = wm * 32 + mt * 16 + (lane >> 2);
                s_red[r * 4 + wn]       = p_lo;
                s_red[(r + 8) * 4 + wn] = p_hi;
            }
        }
    }
    __syncthreads();

    // ---- physics epilogue: threads 0..127, one per row ----
    if (tid < MT) {
        int r = tid;
        float sA = s_red[r * 4 + 0] + s_red[r * 4 + 1];
        float sB = s_red[r * 4 + 2] + s_red[r * 4 + 3];
        float mlpA = sA + bA2[0];
        float mlpB = sB + bB2[0];

        long grow = row0 + r;
        int b   = (int)(grow >> 15);
        int rem = (int)(grow & 32767);
        int l   = rem >> 9;
        int t   = rem & 511;

        const float* lp = lig_pos + ((long)b * NL + l) * 3;
        const float* tp = tgt_pos + ((long)b * NT + t) * 3;
        float dx = lp[0] - tp[0];
        float dy = lp[1] - tp[1];
        float dz = lp[2] - tp[2];
        float dm = sqrtf(dx*dx + dy*dy + dz*dz + 1e-10f);
        if (dm < 0.5f) dm = 1e10f;

        float Bp  = tanhf(mlpB) * 0.2f;
        float dm0 = lig_r[b * NL + l] + tgt_r[b * NT + t] + Bp;
        float dm0c = (dm0 < 1e-4f) ? 1.0f : dm0;
        float ratio = dm0c / dm;
        float r2 = ratio * ratio;
        float r6 = r2 * r2 * r2;
        float vdwe = fminf(fmaf(r6, r6, -2.0f * r6), 100.0f);
        vdwe *= lig_nm[b * NL + l] * tgt_nm[b * NT + t];

        float Av   = 1.0f / (1.0f + expf(-mlpA));
        float Avdw = Av * (0.0356f - 0.0178f) + 0.0178f;
        float v_vdw = Avdw * vdwe;

        float d = dm - dm0;
        const float* ib = inter + (long)b * 3 * NL * NT + (long)l * NT + t;
        float I0 = ib[0];
        float I1 = ib[NL * NT];
        float I2 = ib[2 * NL * NT];
        float v_hb = fminf(fmaxf(d * I0 * (-1.0f / 0.7f), 0.0f), 1.0f);
        float v_mt = fminf(fmaxf(d * I1 * (-1.0f / 0.7f), 0.0f), 1.0f);
        float v_hp = fminf(fmaxf((1.5f - d) * I2, 0.0f), 1.0f);

        #pragma unroll
        for (int off = 16; off > 0; off >>= 1) {
            v_vdw += __shfl_down_sync(0xffffffffu, v_vdw, off);
            v_hb  += __shfl_down_sync(0xffffffffu, v_hb,  off);
            v_mt  += __shfl_down_sync(0xffffffffu, v_mt,  off);
            v_hp  += __shfl_down_sync(0xffffffffu, v_hp,  off);
        }
        if (lane == 0) {
            s_bred[wid * 4 + 0] = v_vdw;
            s_bred[wid * 4 + 1] = v_hb;
            s_bred[wid * 4 + 2] = v_mt;
            s_bred[wid * 4 + 3] = v_hp;
        }
    }
    __syncthreads();
    if (tid < 4) {
        float s = 0.f;
        #pragma unroll
        for (int w = 0; w < 4; w++) s += s_bred[w * 4 + tid];
        g_partial[blockIdx.x][tid] = s;
    }
}

// ---------------- final reduce ----------------
__global__ void energy_reduce_kernel(
    const float* __restrict__ rotor, const float* __restrict__ hb_c,
    const float* __restrict__ hp_c,  const float* __restrict__ rot_c,
    float* __restrict__ out)
{
    int tid = threadIdx.x;
    int b = tid >> 5;
    int k = (tid >> 3) & 3;
    int s = tid & 7;
    const int BLK_PER_B = NBLK / BB;    // 256
    float sum = 0.f;
    for (int i = s; i < BLK_PER_B; i += 8)
        sum += g_partial[b * BLK_PER_B + i][k];
    sum += __shfl_down_sync(0xffffffffu, sum, 4);
    sum += __shfl_down_sync(0xffffffffu, sum, 2);
    sum += __shfl_down_sync(0xffffffffu, sum, 1);
    if (s == 0) {
        float v = sum;
        float hb2 = hb_c[0] * hb_c[0];
        float hp2 = hp_c[0] * hp_c[0];
        if (k == 1 || k == 2) v *= -hb2;
        if (k == 3)           v *= -hp2;
        v /= (1.0f + rot_c[0] * rot_c[0] * rotor[b]);
        out[b * 4 + k] = v;
    }
}

extern "C" void kernel_launch(void* const* d_in, const int* in_sizes, int n_in,
                              void* d_out, int out_size)
{
    const float* lig_pos = (const float*)d_in[0];
    const float* tgt_pos = (const float*)d_in[1];
    const float* lig_r   = (const float*)d_in[2];
    const float* tgt_r   = (const float*)d_in[3];
    const float* lig_nm  = (const float*)d_in[4];
    const float* tgt_nm  = (const float*)d_in[5];
    const float* inter   = (const float*)d_in[6];
    const float* rotor   = (const float*)d_in[7];
    const float* h_cat   = (const float*)d_in[8];
    const float* WA1     = (const float*)d_in[9];
    const float* bA1     = (const float*)d_in[10];
    const float* WA2     = (const float*)d_in[11];
    const float* bA2     = (const float*)d_in[12];
    const float* WB1     = (const float*)d_in[13];
    const float* bB1     = (const float*)d_in[14];
    const float* WB2     = (const float*)d_in[15];
    const float* bB2     = (const float*)d_in[16];
    const float* hb_c    = (const float*)d_in[17];
    const float* hp_c    = (const float*)d_in[18];
    const float* rot_c   = (const float*)d_in[19];
    float* out = (float*)d_out;

    cudaFuncSetAttribute(energy_mma_kernel,
                         cudaFuncAttributeMaxDynamicSharedMemorySize, SMEM_BYTES);

    wt_transpose_kernel<<<256, 256>>>(WA1, WB1);
    energy_mma_kernel<<<NBLK, 512, SMEM_BYTES>>>(
        lig_pos, tgt_pos, lig_r, tgt_r, lig_nm, tgt_nm, inter, h_cat,
        bA1, WA2, bA2, bB1, WB2, bB2);
    energy_reduce_kernel<<<1, 256>>>(rotor, hb_c, hp_c, rot_c, out);
}

// round 7
// speedup vs baseline: 7.9983x; 1.0426x over previous
#include <cuda_runtime.h>
#include <cuda_fp16.h>
#include <math.h>
#include <stdint.h>

// Problem constants
#define BB   8
#define NL   64
#define NT   512
#define KDIM 256
#define MTOT (BB*NL*NT)        // 262144
#define MT   128               // rows per CTA
#define NBLK (MTOT/MT)         // 2048
#define KC   64                // k per chunk
#define WST  36                // smem row stride in 32-bit words (32 data + 4 pad)
#define NTHREADS 256

__device__ float g_partial[NBLK][4];
__device__ __half g_Wt[256 * 256];   // [n][k] fp16

__device__ __forceinline__ uint32_t smem_u32(const void* p) {
    uint32_t a;
    asm("{ .reg .u64 t; cvta.to.shared.u64 t, %1; cvt.u32.u64 %0, t; }" : "=r"(a) : "l"(p));
    return a;
}
__device__ __forceinline__ void cp_async16(uint32_t dst, const void* src) {
    asm volatile("cp.async.ca.shared.global [%0], [%1], 16;" :: "r"(dst), "l"(src) : "memory");
}
__device__ __forceinline__ void cp_commit() {
    asm volatile("cp.async.commit_group;" ::: "memory");
}
__device__ __forceinline__ void cp_wait0() {
    asm volatile("cp.async.wait_group 0;" ::: "memory");
}
__device__ __forceinline__ void mma_f16(float* d, const uint32_t* a, const uint32_t* b) {
    asm volatile(
        "mma.sync.aligned.m16n8k16.row.col.f32.f16.f16.f32 "
        "{%0,%1,%2,%3}, {%4,%5,%6,%7}, {%8,%9}, {%0,%1,%2,%3};"
        : "+f"(d[0]), "+f"(d[1]), "+f"(d[2]), "+f"(d[3])
        : "r"(a[0]), "r"(a[1]), "r"(a[2]), "r"(a[3]), "r"(b[0]), "r"(b[1]));
}

// smem layout (bytes):
#define OFF_BIAS 0
#define OFF_W2   1024
#define OFF_RED  2048
#define OFF_BRED 4096
#define OFF_A    4224
#define A_BYTES  (MT*WST*4)          // 18432
#define OFF_B    (OFF_A + 2*A_BYTES) // 41088
#define B_BYTES  (256*WST*4)         // 36864
#define SMEM_BYTES (OFF_B + 2*B_BYTES)  // 114816

// ---------------- kernel 0: transpose + fp16-round W ----------------
__global__ void wt_transpose_kernel(const float* __restrict__ WA1,
                                    const float* __restrict__ WB1) {
    int n = blockIdx.x;     // 0..255
    int k = threadIdx.x;    // 0..255
    float v = (n < 128) ? WA1[k * 128 + n] : WB1[k * 128 + (n - 128)];
    g_Wt[n * 256 + k] = __float2half_rn(v);
}

// ---------------- main fused kernel ----------------
// 8 warps: wm in {0,1} (64 rows), wn in {0..3} (64 cols). Warp tile 64x64.
__global__ __launch_bounds__(NTHREADS, 1)
void energy_mma_kernel(
    const float* __restrict__ lig_pos, const float* __restrict__ tgt_pos,
    const float* __restrict__ lig_r,   const float* __restrict__ tgt_r,
    const float* __restrict__ lig_nm,  const float* __restrict__ tgt_nm,
    const float* __restrict__ inter,   const float* __restrict__ h_cat,
    const float* __restrict__ bA1, const float* __restrict__ WA2,
    const float* __restrict__ bA2, const float* __restrict__ bB1,
    const float* __restrict__ WB2, const float* __restrict__ bB2)
{
    extern __shared__ char smem[];
    const uint32_t sb = smem_u32(smem);
    const int tid  = threadIdx.x;
    const int wid  = tid >> 5;
    const int lane = tid & 31;
    const int wm   = wid >> 2;     // 0..1 (M)
    const int wn   = wid & 3;      // 0..3 (N)

    float* s_bias = (float*)(smem + OFF_BIAS);
    float* s_w2   = (float*)(smem + OFF_W2);
    float* s_red  = (float*)(smem + OFF_RED);
    float* s_bred = (float*)(smem + OFF_BRED);
    const long row0 = (long)blockIdx.x * MT;

    s_bias[tid] = (tid < 128) ? bA1[tid] : bB1[tid - 128];
    s_w2[tid]   = (tid < 128) ? WA2[tid] : WB2[tid - 128];

    // A staging (LDG fp32 -> regs -> cvt fp16 -> STS): 128 rows x 64 floats
    // = 8192 floats / 256 threads = 32 floats = 8 float4 per thread
    float4 aReg[8];

    auto loadA = [&](int c) {
        #pragma unroll
        for (int i = 0; i < 8; i++) {
            int idx = tid + i * NTHREADS;
            int r = idx >> 4, kq = idx & 15;
            aReg[i] = *(const float4*)(h_cat + (row0 + r) * (long)KDIM + c * KC + kq * 4);
        }
    };
    auto stsA = [&](int buf) {
        uint32_t* Aw = (uint32_t*)(smem + OFF_A + buf * A_BYTES);
        #pragma unroll
        for (int i = 0; i < 8; i++) {
            int idx = tid + i * NTHREADS;
            int r = idx >> 4, kq = idx & 15;
            __half2 h01 = __floats2half2_rn(aReg[i].x, aReg[i].y);
            __half2 h23 = __floats2half2_rn(aReg[i].z, aReg[i].w);
            uint2 u;
            u.x = *(uint32_t*)&h01;
            u.y = *(uint32_t*)&h23;
            *(uint2*)(Aw + r * WST + kq * 2) = u;
        }
    };
    // B: 256 rows x 64 halves = 8 x 16B chunks per row -> 2048 transfers
    auto cpB = [&](int c, int buf) {
        uint32_t dstb = sb + OFF_B + buf * B_BYTES;
        #pragma unroll
        for (int i = 0; i < 8; i++) {
            int idx = tid + i * NTHREADS;  // 0..2047
            int n = idx >> 3, kq = idx & 7;
            cp_async16(dstb + (n * WST + kq * 4) * 4,
                       (const char*)(g_Wt + n * 256 + c * KC + kq * 8));
        }
        cp_commit();
    };

    // prologue: chunk 0
    loadA(0);
    cpB(0, 0);
    stsA(0);
    cp_wait0();
    __syncthreads();

    float acc[4][8][4];
    #pragma unroll
    for (int mt = 0; mt < 4; mt++)
        #pragma unroll
        for (int nt = 0; nt < 8; nt++)
            #pragma unroll
            for (int e = 0; e < 4; e++) acc[mt][nt][e] = 0.0f;

    const int ar0 = wm * 64 + (lane >> 2);
    const int ak  = lane & 3;
    const int bn0 = wn * 64 + (lane >> 2);

    #pragma unroll 1
    for (int c = 0; c < 4; c++) {
        int buf = c & 1, nbuf = buf ^ 1;
        if (c < 3) { loadA(c + 1); cpB(c + 1, nbuf); }

        const uint32_t* Ab = (const uint32_t*)(smem + OFF_A + buf * A_BYTES);
        const uint32_t* Bb = (const uint32_t*)(smem + OFF_B + buf * B_BYTES);

        #pragma unroll
        for (int ks = 0; ks < 4; ks++) {       // 4 x k16 = 64
            int kw = ks * 8 + ak;              // word column (2 halves)
            uint32_t afr[4][4];
            #pragma unroll
            for (int mt = 0; mt < 4; mt++) {
                int rr = ar0 + mt * 16;
                afr[mt][0] = Ab[rr * WST + kw];
                afr[mt][1] = Ab[(rr + 8) * WST + kw];
                afr[mt][2] = Ab[rr * WST + kw + 4];
                afr[mt][3] = Ab[(rr + 8) * WST + kw + 4];
            }
            uint32_t bfr[8][2];
            #pragma unroll
            for (int nt = 0; nt < 8; nt++) {
                int nn = bn0 + nt * 8;
                bfr[nt][0] = Bb[nn * WST + kw];
                bfr[nt][1] = Bb[nn * WST + kw + 4];
            }
            #pragma unroll
            for (int mt = 0; mt < 4; mt++)
                #pragma unroll
                for (int nt = 0; nt < 8; nt++)
                    mma_f16(acc[mt][nt], afr[mt], bfr[nt]);
        }

        if (c < 3) { stsA(nbuf); cp_wait0(); }
        __syncthreads();
    }

    // ---- epilogue: relu(acc+bias) . w2, per-row sums ----
    {
        #pragma unroll
        for (int mt = 0; mt < 4; mt++) {
            float p_lo = 0.f, p_hi = 0.f;
            #pragma unroll
            for (int nt = 0; nt < 8; nt++) {
                int cb = wn * 64 + nt * 8 + 2 * (lane & 3);
                float b0 = s_bias[cb],     w0 = s_w2[cb];
                float b1 = s_bias[cb + 1], w1 = s_w2[cb + 1];
                p_lo = fmaf(fmaxf(acc[mt][nt][0] + b0, 0.f), w0, p_lo);
                p_lo = fmaf(fmaxf(acc[mt][nt][1] + b1, 0.f), w1, p_lo);
                p_hi = fmaf(fmaxf(acc[mt][nt][2] + b0, 0.f), w0, p_hi);
                p_hi = fmaf(fmaxf(acc[mt][nt][3] + b1, 0.f), w1, p_hi);
            }
            p_lo += __shfl_xor_sync(0xffffffffu, p_lo, 1);
            p_lo += __shfl_xor_sync(0xffffffffu, p_lo, 2);
            p_hi += __shfl_xor_sync(0xffffffffu, p_hi, 1);
            p_hi += __shfl_xor_sync(0xffffffffu, p_hi, 2);
            if ((lane & 3) == 0) {
                int r = wm * 64 + mt * 16 + (lane >> 2);
                s_red[r * 4 + wn]       = p_lo;
                s_red[(r + 8) * 4 + wn] = p_hi;
            }
        }
    }
    __syncthreads();

    // ---- physics epilogue: threads 0..127, one per row ----
    if (tid < MT) {
        int r = tid;
        float sA = s_red[r * 4 + 0] + s_red[r * 4 + 1];
        float sB = s_red[r * 4 + 2] + s_red[r * 4 + 3];
        float mlpA = sA + bA2[0];
        float mlpB = sB + bB2[0];

        long grow = row0 + r;
        int b   = (int)(grow >> 15);
        int rem = (int)(grow & 32767);
        int l   = rem >> 9;
        int t   = rem & 511;

        const float* lp = lig_pos + ((long)b * NL + l) * 3;
        const float* tp = tgt_pos + ((long)b * NT + t) * 3;
        float dx = lp[0] - tp[0];
        float dy = lp[1] - tp[1];
        float dz = lp[2] - tp[2];
        float dm = sqrtf(dx*dx + dy*dy + dz*dz + 1e-10f);
        if (dm < 0.5f) dm = 1e10f;

        float Bp  = tanhf(mlpB) * 0.2f;
        float dm0 = lig_r[b * NL + l] + tgt_r[b * NT + t] + Bp;
        float dm0c = (dm0 < 1e-4f) ? 1.0f : dm0;
        float ratio = dm0c / dm;
        float r2 = ratio * ratio;
        float r6 = r2 * r2 * r2;
        float vdwe = fminf(fmaf(r6, r6, -2.0f * r6), 100.0f);
        vdwe *= lig_nm[b * NL + l] * tgt_nm[b * NT + t];

        float Av   = 1.0f / (1.0f + expf(-mlpA));
        float Avdw = Av * (0.0356f - 0.0178f) + 0.0178f;
        float v_vdw = Avdw * vdwe;

        float d = dm - dm0;
        const float* ib = inter + (long)b * 3 * NL * NT + (long)l * NT + t;
        float I0 = ib[0];
        float I1 = ib[NL * NT];
        float I2 = ib[2 * NL * NT];
        float v_hb = fminf(fmaxf(d * I0 * (-1.0f / 0.7f), 0.0f), 1.0f);
        float v_mt = fminf(fmaxf(d * I1 * (-1.0f / 0.7f), 0.0f), 1.0f);
        float v_hp = fminf(fmaxf((1.5f - d) * I2, 0.0f), 1.0f);

        #pragma unroll
        for (int off = 16; off > 0; off >>= 1) {
            v_vdw += __shfl_down_sync(0xffffffffu, v_vdw, off);
            v_hb  += __shfl_down_sync(0xffffffffu, v_hb,  off);
            v_mt  += __shfl_down_sync(0xffffffffu, v_mt,  off);
            v_hp  += __shfl_down_sync(0xffffffffu, v_hp,  off);
        }
        if (lane == 0) {
            s_bred[wid * 4 + 0] = v_vdw;
            s_bred[wid * 4 + 1] = v_hb;
            s_bred[wid * 4 + 2] = v_mt;
            s_bred[wid * 4 + 3] = v_hp;
        }
    }
    __syncthreads();
    if (tid < 4) {
        float s = 0.f;
        #pragma unroll
        for (int w = 0; w < 4; w++) s += s_bred[w * 4 + tid];
        g_partial[blockIdx.x][tid] = s;
    }
}

// ---------------- final reduce ----------------
__global__ void energy_reduce_kernel(
    const float* __restrict__ rotor, const float* __restrict__ hb_c,
    const float* __restrict__ hp_c,  const float* __restrict__ rot_c,
    float* __restrict__ out)
{
    int tid = threadIdx.x;
    int b = tid >> 5;
    int k = (tid >> 3) & 3;
    int s = tid & 7;
    const int BLK_PER_B = NBLK / BB;    // 256
    float sum = 0.f;
    for (int i = s; i < BLK_PER_B; i += 8)
        sum += g_partial[b * BLK_PER_B + i][k];
    sum += __shfl_down_sync(0xffffffffu, sum, 4);
    sum += __shfl_down_sync(0xffffffffu, sum, 2);
    sum += __shfl_down_sync(0xffffffffu, sum, 1);
    if (s == 0) {
        float v = sum;
        float hb2 = hb_c[0] * hb_c[0];
        float hp2 = hp_c[0] * hp_c[0];
        if (k == 1 || k == 2) v *= -hb2;
        if (k == 3)           v *= -hp2;
        v /= (1.0f + rot_c[0] * rot_c[0] * rotor[b]);
        out[b * 4 + k] = v;
    }
}

extern "C" void kernel_launch(void* const* d_in, const int* in_sizes, int n_in,
                              void* d_out, int out_size)
{
    const float* lig_pos = (const float*)d_in[0];
    const float* tgt_pos = (const float*)d_in[1];
    const float* lig_r   = (const float*)d_in[2];
    const float* tgt_r   = (const float*)d_in[3];
    const float* lig_nm  = (const float*)d_in[4];
    const float* tgt_nm  = (const float*)d_in[5];
    const float* inter   = (const float*)d_in[6];
    const float* rotor   = (const float*)d_in[7];
    const float* h_cat   = (const float*)d_in[8];
    const float* WA1     = (const float*)d_in[9];
    const float* bA1     = (const float*)d_in[10];
    const float* WA2     = (const float*)d_in[11];
    const float* bA2     = (const float*)d_in[12];
    const float* WB1     = (const float*)d_in[13];
    const float* bB1     = (const float*)d_in[14];
    const float* WB2     = (const float*)d_in[15];
    const float* bB2     = (const float*)d_in[16];
    const float* hb_c    = (const float*)d_in[17];
    const float* hp_c    = (const float*)d_in[18];
    const float* rot_c   = (const float*)d_in[19];
    float* out = (float*)d_out;

    cudaFuncSetAttribute(energy_mma_kernel,
                         cudaFuncAttributeMaxDynamicSharedMemorySize, SMEM_BYTES);

    wt_transpose_kernel<<<256, 256>>>(WA1, WB1);
    energy_mma_kernel<<<NBLK, NTHREADS, SMEM_BYTES>>>(
        lig_pos, tgt_pos, lig_r, tgt_r, lig_nm, tgt_nm, inter, h_cat,
        bA1, WA2, bA2, bB1, WB2, bB2);
    energy_reduce_kernel<<<1, 256>>>(rotor, hb_c, hp_c, rot_c, out);
}